// round 10
// baseline (speedup 1.0000x reference)
#include <cuda_runtime.h>

namespace {
constexpr int S_TOT   = 22743;           // 3*(76^2 + 38^2 + 19^2)
constexpr int S1      = 17328;           // 76*76*3
constexpr int C       = 85;
constexpr int LEN     = S1 * C;          // 1,472,880 dense floats per batch
constexpr int STRIDEB = S_TOT * C;       // 1,933,155 floats per batch (≡3 mod 8)
constexpr int V8U     = (LEN - 7) / 8;   // 184,109 uniform float8s per batch
constexpr int TPB     = 256;
constexpr int MINBPM  = 4;               // 64 regs/thread budget
constexpr int MAXNB   = 4096;
constexpr unsigned PRIM_BYTES = 112u << 20;  // 112 MB of tg pinned evict_last
}

__device__ float    g_partials[MAXNB * 5];
__device__ unsigned g_count = 0;

// Range policy: tg[0, prim) -> evict_last, tg[prim, tot) -> evict_first
__device__ __forceinline__ unsigned long long mk_policy_range(const void* base,
                                                              unsigned prim,
                                                              unsigned tot) {
    unsigned long long pol;
    asm("createpolicy.range.global.L2::evict_last.L2::evict_first.b64 %0, [%1], %2, %3;"
        : "=l"(pol) : "l"(base), "r"(prim), "r"(tot));
    return pol;
}
// Fractional evict_first policy for the pure streaming x tensor
__device__ __forceinline__ unsigned long long mk_policy_ef() {
    unsigned long long pol;
    asm("createpolicy.fractional.L2::evict_first.b64 %0, 1.0;" : "=l"(pol));
    return pol;
}

// 256-bit global load with cache policy
__device__ __forceinline__ void ld_v8(const float* p, unsigned long long pol,
                                      float r[8]) {
    unsigned u0,u1,u2,u3,u4,u5,u6,u7;
    asm("ld.global.nc.L2::cache_hint.v8.b32 {%0,%1,%2,%3,%4,%5,%6,%7}, [%8], %9;"
        : "=r"(u0),"=r"(u1),"=r"(u2),"=r"(u3),
          "=r"(u4),"=r"(u5),"=r"(u6),"=r"(u7)
        : "l"(p), "l"(pol));
    r[0]=__uint_as_float(u0); r[1]=__uint_as_float(u1);
    r[2]=__uint_as_float(u2); r[3]=__uint_as_float(u3);
    r[4]=__uint_as_float(u4); r[5]=__uint_as_float(u5);
    r[6]=__uint_as_float(u6); r[7]=__uint_as_float(u7);
}
__device__ __forceinline__ float ld_el1(const float* p, unsigned long long pol) {
    float v;
    asm("ld.global.nc.L2::cache_hint.f32 %0, [%1], %2;" : "=f"(v) : "l"(p), "l"(pol));
    return v;
}

// BCE in log2 units: final loss = -ln2 * sum
__device__ __forceinline__ float bce_l2(float p, float t) {
    float lp = __log2f(p);
    float lq = __log2f(1.0f - p);
    return fmaf(t, lp - lq, lq);
}
__device__ __forceinline__ float bce8_l2(const float p[8], const float t[8]) {
    float s0 = bce_l2(p[0], t[0]) + bce_l2(p[1], t[1]);
    float s1 = bce_l2(p[2], t[2]) + bce_l2(p[3], t[3]);
    float s2 = bce_l2(p[4], t[4]) + bce_l2(p[5], t[5]);
    float s3 = bce_l2(p[6], t[6]) + bce_l2(p[7], t[7]);
    return (s0 + s1) + (s2 + s3);
}

__global__ __launch_bounds__(TPB, MINBPM)
void yolo_fused(const float* __restrict__ x,
                const float* __restrict__ tg,
                int B, float inv_obj_div,
                unsigned tg_bytes,
                float* __restrict__ out) {
    const int gtid = blockIdx.x * TPB + threadIdx.x;
    const int NT   = gridDim.x * TPB;
    const int W8   = B * V8U;
    const int rows = B * S_TOT;
    const unsigned long long POLT = mk_policy_range(tg, PRIM_BYTES, tg_bytes);
    const unsigned long long POLX = mk_policy_ef();

    float a_obj = 0.f, a_xy = 0.f, a_wh = 0.f, a_cls = 0.f, a_cnt = 0.f;

    // ── Prefetch Pass-B probes (latency hidden under Pass A) ──
    const int r0 = gtid;           // always < rows (NT << rows)
    const int r1 = gtid + NT;
    float pf0 = ld_el1(tg + r0 * C + 4, POLT);
    float pf1 = (r1 < rows) ? ld_el1(tg + r1 * C + 4, POLT) : 0.0f;

    // ── Pass A: flat dense-slab BCE in float8 units, batch carried
    //    incrementally. base_b ≡ 3b (mod 8); pad' = (pad+5)&7. ──
    int v = gtid, pad = 0, off8 = 0;

#define YSTEP8()                                                   \
    do {                                                           \
        v += NT;                                                   \
        if (v >= V8U) {                                            \
            v -= V8U;                                              \
            int dp = ((pad + 5) & 7) - pad;                        \
            off8 += (STRIDEB + dp) >> 3;                           \
            pad += dp;                                             \
        }                                                          \
    } while (0)

    int w = gtid;
    for (; w + NT < W8; w += 2 * NT) {
        int a0 = off8 + v; YSTEP8();
        int a1 = off8 + v; YSTEP8();
        float p0[8], q0[8], p1[8], q1[8];
        ld_v8(x  + ((size_t)a0 << 3), POLX, p0);
        ld_v8(tg + ((size_t)a0 << 3), POLT, q0);
        ld_v8(x  + ((size_t)a1 << 3), POLX, p1);
        ld_v8(tg + ((size_t)a1 << 3), POLT, q1);
        a_obj += bce8_l2(p0, q0) + bce8_l2(p1, q1);
    }
    for (; w < W8; w += NT) {
        int a0 = off8 + v; YSTEP8();
        float p0[8], q0[8];
        ld_v8(x  + ((size_t)a0 << 3), POLX, p0);
        ld_v8(tg + ((size_t)a0 << 3), POLT, q0);
        a_obj += bce8_l2(p0, q0);
    }
#undef YSTEP8

    // leftover scalars: exactly 8 per batch (head pad + tail 8-pad)
    if (gtid < 8 * B) {
        int bb   = gtid >> 3, j = gtid & 7;
        int base = bb * STRIDEB;
        int pd   = (8 - ((bb * 3) & 7)) & 7;     // = (8 - (base&7)) & 7
        int idx  = (j < pd) ? (base + j)
                            : (base + pd + 8 * V8U + (j - pd));
        a_obj += bce_l2(x[idx], ld_el1(tg + idx, POLT));
    }

    // ── Pass B: gated xy/wh/cls terms (probes already in flight) ──
    {
        if (pf0 > 0.0f) {
            const int rb = r0 * C;
            a_xy  += bce_l2(__ldg(x + rb + 0), ld_el1(tg + rb + 0, POLT))
                   + bce_l2(__ldg(x + rb + 1), ld_el1(tg + rb + 1, POLT));
            a_wh  += bce_l2(__ldg(x + rb + 2), ld_el1(tg + rb + 2, POLT))
                   + bce_l2(__ldg(x + rb + 3), ld_el1(tg + rb + 3, POLT));
            a_cls += bce_l2(__ldg(x + rb + 4), pf0);
            a_cnt += 1.0f;
        }
        if (r1 < rows && pf1 > 0.0f) {
            const int rb = r1 * C;
            a_xy  += bce_l2(__ldg(x + rb + 0), ld_el1(tg + rb + 0, POLT))
                   + bce_l2(__ldg(x + rb + 1), ld_el1(tg + rb + 1, POLT));
            a_wh  += bce_l2(__ldg(x + rb + 2), ld_el1(tg + rb + 2, POLT))
                   + bce_l2(__ldg(x + rb + 3), ld_el1(tg + rb + 3, POLT));
            a_cls += bce_l2(__ldg(x + rb + 4), pf1);
            a_cnt += 1.0f;
        }
        for (int r = gtid + 2 * NT; r < rows; r += NT) {
            const int rb = r * C;
            float t4v = ld_el1(tg + rb + 4, POLT);
            if (t4v > 0.0f) {
                a_xy  += bce_l2(x[rb + 0], ld_el1(tg + rb + 0, POLT))
                       + bce_l2(x[rb + 1], ld_el1(tg + rb + 1, POLT));
                a_wh  += bce_l2(x[rb + 2], ld_el1(tg + rb + 2, POLT))
                       + bce_l2(x[rb + 3], ld_el1(tg + rb + 3, POLT));
                a_cls += bce_l2(x[rb + 4], t4v);
                a_cnt += 1.0f;
            }
        }
    }

    // ── block reduction (5 scalars) ──
    const int lane = threadIdx.x & 31;
    const int wid  = threadIdx.x >> 5;
    #pragma unroll
    for (int off = 16; off; off >>= 1) {
        a_obj += __shfl_xor_sync(0xffffffffu, a_obj, off);
        a_xy  += __shfl_xor_sync(0xffffffffu, a_xy,  off);
        a_wh  += __shfl_xor_sync(0xffffffffu, a_wh,  off);
        a_cls += __shfl_xor_sync(0xffffffffu, a_cls, off);
        a_cnt += __shfl_xor_sync(0xffffffffu, a_cnt, off);
    }
    __shared__ float sm[TPB / 32][5];
    if (lane == 0) {
        sm[wid][0] = a_obj; sm[wid][1] = a_xy; sm[wid][2] = a_wh;
        sm[wid][3] = a_cls; sm[wid][4] = a_cnt;
    }
    __syncthreads();
    if (threadIdx.x < 32) {
        #pragma unroll
        for (int k = 0; k < 5; k++) {
            float vv = (lane < TPB / 32) ? sm[lane][k] : 0.0f;
            #pragma unroll
            for (int off = 4; off; off >>= 1)
                vv += __shfl_xor_sync(0xffffffffu, vv, off);
            if (lane == 0) g_partials[blockIdx.x * 5 + k] = vv;
        }
    }

    // ── last-block final reduction ──
    __shared__ bool isLast;
    if (threadIdx.x == 0) {
        __threadfence();
        unsigned old = atomicAdd(&g_count, 1u);
        isLast = (old == gridDim.x - 1u);
    }
    __syncthreads();
    if (isLast) {
        const volatile float* gp = g_partials;
        float loc[5] = {0.f, 0.f, 0.f, 0.f, 0.f};
        for (int j = threadIdx.x; j < (int)gridDim.x; j += TPB) {
            #pragma unroll
            for (int k = 0; k < 5; k++) loc[k] += gp[j * 5 + k];
        }
        __shared__ float red[TPB];
        float tot[5];
        #pragma unroll
        for (int k = 0; k < 5; k++) {
            red[threadIdx.x] = loc[k];
            __syncthreads();
            for (int st = TPB / 2; st; st >>= 1) {
                if (threadIdx.x < st) red[threadIdx.x] += red[threadIdx.x + st];
                __syncthreads();
            }
            tot[k] = red[0];
            __syncthreads();
        }
        if (threadIdx.x == 0) {
            constexpr float LN2 = 0.69314718055994530942f;
            float cnt   = fmaxf(tot[4], 1.0f);
            float inv_c = 1.0f / cnt;
            out[0] = -LN2 * (tot[0] * inv_obj_div
                             + (tot[1] + tot[2]) * 0.5f * inv_c
                             + tot[3] * inv_c);
            g_count = 0;
        }
    }
}

extern "C" void kernel_launch(void* const* d_in, const int* in_sizes, int n_in,
                              void* d_out, int out_size) {
    const float* x  = (const float*)d_in[0];
    const float* tg = (const float*)d_in[1];
    const int rows  = in_sizes[0] / C;     // B * S
    const int Bn    = rows / S_TOT;        // batch
    const float inv_obj_div = 1.0f / ((float)Bn * (float)S1 * (float)C);
    const unsigned tg_bytes = (unsigned)in_sizes[1] * 4u;

    int dev = 0, smCount = 148, bpm = MINBPM;
    cudaGetDevice(&dev);
    cudaDeviceGetAttribute(&smCount, cudaDevAttrMultiProcessorCount, dev);
    cudaOccupancyMaxActiveBlocksPerMultiprocessor(&bpm, yolo_fused, TPB, 0);
    int nb = smCount * (bpm > 0 ? bpm : 1);
    if (nb > MAXNB) nb = MAXNB;

    yolo_fused<<<nb, TPB>>>(x, tg, Bn, inv_obj_div, tg_bytes, (float*)d_out);
}